// round 1
// baseline (speedup 1.0000x reference)
#include <cuda_runtime.h>
#include <math.h>

#define NPTS   2048
#define IDIM   16
#define HDIM   32
#define CUTSN  8
#define JSPLIT 32
#define TILE_I 128
#define JCHUNK (NPTS / JSPLIT)   // 64

// ---------------- device scratch (no allocations allowed) ----------------
__device__ float g_pts[NPTS * 3];
__device__ float g_nrm[NPTS * 3];
__device__ float g_f  [NPTS * HDIM];                 // normalized net_in output
__device__ float g_z  [NPTS * HDIM];                 // pre-norm scratch (reused)
__device__ float g_mid[NPTS * HDIM];                 // pairwise interaction result
__device__ float g_partial[JSPLIT][NPTS * HDIM];     // 8 MB partial sums
__device__ float g_stats[8];                         // mu[0..3], rstd[4..7]

__device__ __forceinline__ float leakyf(float x) { return x >= 0.f ? x : 0.2f * x; }

// ---------------- prep: scaled points + normals = nuv[:,0,:] ----------------
__global__ void k_prep(const float* __restrict__ points, const float* __restrict__ nuv) {
    int i = blockIdx.x * blockDim.x + threadIdx.x;
    if (i >= NPTS) return;
    const float s = 0.07856742013183862f;  // 1/(sqrt(2)*9)
    g_pts[i * 3 + 0] = points[i * 3 + 0] * s;
    g_pts[i * 3 + 1] = points[i * 3 + 1] * s;
    g_pts[i * 3 + 2] = points[i * 3 + 2] * s;
    g_nrm[i * 3 + 0] = nuv[i * 9 + 0];
    g_nrm[i * 3 + 1] = nuv[i * 9 + 1];
    g_nrm[i * 3 + 2] = nuv[i * 9 + 2];
}

// ---------------- two-layer leaky MLP (per point row) ----------------
template <int IN>
__global__ void k_net(const float* __restrict__ x,
                      const float* __restrict__ W1, const float* __restrict__ b1,
                      const float* __restrict__ W2, const float* __restrict__ b2,
                      float* __restrict__ out) {
    __shared__ float sW1[HDIM * IN], sW2[HDIM * HDIM], sb1[HDIM], sb2[HDIM];
    int tid = threadIdx.x;
    for (int k = tid; k < HDIM * IN;   k += blockDim.x) sW1[k] = W1[k];
    for (int k = tid; k < HDIM * HDIM; k += blockDim.x) sW2[k] = W2[k];
    if (tid < HDIM) { sb1[tid] = b1[tid]; sb2[tid] = b2[tid]; }
    __syncthreads();

    int n = blockIdx.x * blockDim.x + tid;
    if (n >= NPTS) return;

    float xi[IN];
#pragma unroll
    for (int i = 0; i < IN; i++) xi[i] = x[n * IN + i];

    float z1[HDIM];
#pragma unroll
    for (int h = 0; h < HDIM; h++) {
        float s = sb1[h];
#pragma unroll
        for (int i = 0; i < IN; i++) s += sW1[h * IN + i] * xi[i];
        z1[h] = leakyf(s);
    }
#pragma unroll
    for (int h = 0; h < HDIM; h++) {
        float s = sb2[h];
#pragma unroll
        for (int c = 0; c < HDIM; c++) s += sW2[h * HDIM + c] * z1[c];
        out[n * HDIM + h] = leakyf(s);
    }
}

// ---------------- group-norm stats: 4 groups of 8 channels x N points ----------------
__global__ void k_gstats(const float* __restrict__ z) {
    __shared__ double ssum[4][256];
    __shared__ double ssq [4][256];
    int tid = threadIdx.x;
    double s[4] = {0, 0, 0, 0}, q[4] = {0, 0, 0, 0};
    for (int n = tid; n < NPTS; n += 256) {
#pragma unroll
        for (int c = 0; c < HDIM; c++) {
            float v = z[n * HDIM + c];
            int g = c >> 3;
            s[g] += (double)v;
            q[g] += (double)v * (double)v;
        }
    }
#pragma unroll
    for (int g = 0; g < 4; g++) { ssum[g][tid] = s[g]; ssq[g][tid] = q[g]; }
    __syncthreads();
    for (int off = 128; off; off >>= 1) {
        if (tid < off) {
#pragma unroll
            for (int g = 0; g < 4; g++) {
                ssum[g][tid] += ssum[g][tid + off];
                ssq [g][tid] += ssq [g][tid + off];
            }
        }
        __syncthreads();
    }
    if (tid < 4) {
        double cnt = (double)NPTS * 8.0;
        double mu  = ssum[tid][0] / cnt;
        double var = ssq[tid][0] / cnt - mu * mu;
        g_stats[tid]     = (float)mu;
        g_stats[4 + tid] = (float)(1.0 / sqrt(var + 1e-5));
    }
}

// ---------------- apply group norm ----------------
__global__ void k_gnorm(const float* __restrict__ z, const float* __restrict__ gamma,
                        const float* __restrict__ beta, float* __restrict__ out) {
    int idx = blockIdx.x * blockDim.x + threadIdx.x;
    if (idx >= NPTS * HDIM) return;
    int c = idx & (HDIM - 1);
    int g = c >> 3;
    out[idx] = (z[idx] - g_stats[g]) * g_stats[4 + g] * gamma[c] + beta[c];
}

// ---------------- the O(N^2) pairwise interaction ----------------
__global__ void __launch_bounds__(TILE_I) k_pair(const float* __restrict__ nuv,
                                                 const float* __restrict__ A1,
                                                 const float* __restrict__ B1,
                                                 const float* __restrict__ A2,
                                                 const float* __restrict__ B2) {
    __shared__ float  sPt[JCHUNK][3];
    __shared__ float  sNr[JCHUNK][3];
    __shared__ float  sF [JCHUNK][HDIM];
    __shared__ float4 sA2[HDIM * 2];
    __shared__ float  sB2[HDIM];

    int tid = threadIdx.x;
    int j0  = blockIdx.y * JCHUNK;

    for (int k = tid; k < JCHUNK * 3; k += TILE_I) {
        sPt[k / 3][k % 3] = g_pts[j0 * 3 + k];
        sNr[k / 3][k % 3] = g_nrm[j0 * 3 + k];
    }
    for (int k = tid; k < JCHUNK * HDIM; k += TILE_I)
        sF[k / HDIM][k % HDIM] = g_f[j0 * HDIM + k];
    if (tid < HDIM * 2) sA2[tid] = ((const float4*)A2)[tid];
    if (tid < HDIM)     sB2[tid] = B2[tid];
    __syncthreads();

    int i = blockIdx.x * TILE_I + tid;
    float px = g_pts[i * 3 + 0], py = g_pts[i * 3 + 1], pz = g_pts[i * 3 + 2];
    float nx = g_nrm[i * 3 + 0], ny = g_nrm[i * 3 + 1], nz = g_nrm[i * 3 + 2];
    float u[9];
#pragma unroll
    for (int k = 0; k < 9; k++) u[k] = nuv[i * 9 + k];
    float a1r[CUTSN * 3], b1r[CUTSN];
#pragma unroll
    for (int k = 0; k < CUTSN * 3; k++) a1r[k] = A1[k];
#pragma unroll
    for (int k = 0; k < CUTSN; k++) b1r[k] = B1[k];

    float acc[HDIM];
#pragma unroll
    for (int h = 0; h < HDIM; h++) acc[h] = 0.f;

    for (int jj = 0; jj < JCHUNK; jj++) {
        float dx = sPt[jj][0] - px, dy = sPt[jj][1] - py, dz = sPt[jj][2] - pz;
        float sq  = dx * dx + dy * dy + dz * dz;
        float dot = nx * sNr[jj][0] + ny * sNr[jj][1] + nz * sNr[jj][2];
        float t   = 2.f - dot;
        float w   = __expf(-sq * t * t);

        float X0 = u[0] * dx + u[1] * dy + u[2] * dz;
        float X1 = u[3] * dx + u[4] * dy + u[5] * dz;
        float X2 = u[6] * dx + u[7] * dy + u[8] * dz;

        float xc[CUTSN];
#pragma unroll
        for (int c = 0; c < CUTSN; c++) {
            float s = b1r[c] + a1r[c * 3] * X0 + a1r[c * 3 + 1] * X1 + a1r[c * 3 + 2] * X2;
            xc[c] = fmaxf(s, 0.f);
        }
#pragma unroll
        for (int h = 0; h < HDIM; h++) {
            float4 a = sA2[h * 2], b = sA2[h * 2 + 1];
            float s = sB2[h] + a.x * xc[0] + a.y * xc[1] + a.z * xc[2] + a.w * xc[3]
                             + b.x * xc[4] + b.y * xc[5] + b.z * xc[6] + b.w * xc[7];
            s = fmaxf(s, 0.f);
            acc[h] += (w * sF[jj][h]) * s;
        }
    }

    float* outp = &g_partial[blockIdx.y][i * HDIM];
#pragma unroll
    for (int h = 0; h < HDIM; h++) outp[h] = acc[h];
}

// ---------------- deterministic reduce over j-splits ----------------
__global__ void k_reduce() {
    int idx = blockIdx.x * blockDim.x + threadIdx.x;
    if (idx >= NPTS * HDIM) return;
    float s = 0.f;
#pragma unroll
    for (int p = 0; p < JSPLIT; p++) s += g_partial[p][idx];
    g_mid[idx] = s;
}

// ---------------- launch ----------------
extern "C" void kernel_launch(void* const* d_in, const int* in_sizes, int n_in,
                              void* d_out, int out_size) {
    const float* points  = (const float*)d_in[0];
    const float* nuv     = (const float*)d_in[1];
    const float* feats   = (const float*)d_in[2];
    const float* W_in1   = (const float*)d_in[3];
    const float* b_in1   = (const float*)d_in[4];
    const float* W_in2   = (const float*)d_in[5];
    const float* b_in2   = (const float*)d_in[6];
    const float* g_in_w  = (const float*)d_in[7];
    const float* g_in_b  = (const float*)d_in[8];
    const float* A1      = (const float*)d_in[9];
    const float* A2      = (const float*)d_in[10];
    const float* W_out1  = (const float*)d_in[11];
    const float* b_out1  = (const float*)d_in[12];
    const float* W_out2  = (const float*)d_in[13];
    const float* b_out2  = (const float*)d_in[14];
    const float* g_out_w = (const float*)d_in[15];
    const float* g_out_b = (const float*)d_in[16];
    const float* B1      = (const float*)d_in[17];
    const float* B2      = (const float*)d_in[18];

    float *p_f, *p_z, *p_mid;
    cudaGetSymbolAddress((void**)&p_f,   g_f);
    cudaGetSymbolAddress((void**)&p_z,   g_z);
    cudaGetSymbolAddress((void**)&p_mid, g_mid);

    // 1) prep scaled points + normals
    k_prep<<<NPTS / 128, 128>>>(points, nuv);
    // 2) net_in + group norm
    k_net<IDIM><<<NPTS / 128, 128>>>(feats, W_in1, b_in1, W_in2, b_in2, p_z);
    k_gstats<<<1, 256>>>(p_z);
    k_gnorm<<<(NPTS * HDIM) / 256, 256>>>(p_z, g_in_w, g_in_b, p_f);
    // 3) pairwise interaction
    k_pair<<<dim3(NPTS / TILE_I, JSPLIT), TILE_I>>>(nuv, A1, B1, A2, B2);
    k_reduce<<<(NPTS * HDIM) / 256, 256>>>();
    // 4) net_out + group norm -> d_out
    k_net<HDIM><<<NPTS / 128, 128>>>(p_mid, W_out1, b_out1, W_out2, b_out2, p_z);
    k_gstats<<<1, 256>>>(p_z);
    k_gnorm<<<(NPTS * HDIM) / 256, 256>>>(p_z, g_out_w, g_out_b, (float*)d_out);
}